// round 15
// baseline (speedup 1.0000x reference)
#include <cuda_runtime.h>
#include <math.h>
#include <stdint.h>

#define NB   8
#define L    5000
#define DIN  12
#define H    256
#define N2   32
#define NL   6
#define NC   64
#define CT   79
#define BL   (NB*L)
#define NP   16

typedef unsigned long long ull;

__device__ __forceinline__ ull fma2(ull a, ull b, ull c){ ull d; asm("fma.rn.f32x2 %0,%1,%2,%3;":"=l"(d):"l"(a),"l"(b),"l"(c)); return d; }
__device__ __forceinline__ ull mul2(ull a, ull b){ ull d; asm("mul.rn.f32x2 %0,%1,%2;":"=l"(d):"l"(a),"l"(b)); return d; }
__device__ __forceinline__ ull pk2(float lo, float hi){ ull r; asm("mov.b64 %0,{%1,%2};":"=l"(r):"f"(lo),"f"(hi)); return r; }
__device__ __forceinline__ void upk2(ull v, float& lo, float& hi){ asm("mov.b64 {%0,%1},%2;":"=f"(lo),"=f"(hi):"l"(v)); }
__device__ __forceinline__ void cpa16(uint32_t dst, const float* src){
    asm volatile("cp.async.cg.shared.global [%0], [%1], 16;"::"r"(dst),"l"(src));
}
__device__ __forceinline__ void cpa_commit(){ asm volatile("cp.async.commit_group;"); }
__device__ __forceinline__ void cpa_wait0(){ asm volatile("cp.async.wait_group 0;"); }
__device__ __forceinline__ float gelu1(float y){ return 0.5f*y*(1.0f + erff(y*0.70710678118654752f)); }

// ---- scratch ----
__device__ float  g_h[NB*H*L];
__device__ float  g_yg[H*BL + 128];
__device__ float4 g_pk1[NL*H*NP];   // rr0,rr1,ri0,ri1
__device__ float4 g_pk2[NL*H*NP];   // -ri0,-ri1,cr0,cr1
__device__ float2 g_pk3[NL*H*NP];   // ci0,ci1
__device__ float2 g_r  [NL*H*N2];
__device__ float  g_bnscale[H];
__device__ float  g_bnshift[H];
__device__ double g_bnsum[H];
__device__ double g_bnsq[H];

__global__ void params_kernel(const float* __restrict__ log_dt, const float* __restrict__ C_re,
                              const float* __restrict__ C_im, const float* __restrict__ logA,
                              const float* __restrict__ Aim){
    int idx = blockIdx.x*blockDim.x + threadIdx.x;
    if (idx >= NL*H*NP) return;
    int np = idx & (NP-1);
    int lh = idx >> 4;
    float dt = expf(log_dt[lh]);
    float rr[2], ri[2], cr[2], ci[2];
#pragma unroll
    for (int k = 0; k < 2; k++){
        int pi = lh*N2 + np + k*16;
        float Ar = -expf(logA[pi]);
        float Ai = Aim[pi];
        float er = expf(dt*Ar);
        float rre = er*cosf(dt*Ai), rim = er*sinf(dt*Ai);
        float e1r = rre - 1.0f, e1i = rim;
        float cre = C_re[pi], cim = C_im[pi];
        float tr = cre*e1r - cim*e1i;
        float ti = cre*e1i + cim*e1r;
        float inv = 1.0f/(Ar*Ar + Ai*Ai);
        float Cdr = (tr*Ar + ti*Ai)*inv;
        float Cdi = (ti*Ar - tr*Ai)*inv;
        rr[k]=rre; ri[k]=rim; cr[k]=2.0f*Cdr; ci[k]=2.0f*Cdi;
        g_r[pi] = make_float2(rre, rim);
    }
    g_pk1[idx] = make_float4(rr[0], rr[1], ri[0], ri[1]);
    g_pk2[idx] = make_float4(-ri[0], -ri[1], cr[0], cr[1]);
    g_pk3[idx] = make_float2(ci[0], ci[1]);
}

__global__ void preproj_kernel(const float* __restrict__ x, const float* __restrict__ w,
                               const float* __restrict__ bias){
    __shared__ float xs[128*13];
    __shared__ float ws[H*12];
    __shared__ float bs[H];
    int b = blockIdx.y;
    int l0 = blockIdx.x*128;
    int tid = threadIdx.x;
    for (int i = tid; i < H*12; i += 128) ws[i] = w[i];
    for (int i = tid; i < H;    i += 128) bs[i] = bias[i];
    for (int i = tid; i < 128*12; i += 128){
        int ll = i/12, d = i - ll*12;
        int l = l0 + ll;
        xs[ll*13+d] = (l < L) ? x[(b*L + l)*12 + d] : 0.0f;
    }
    __syncthreads();
    int l = l0 + tid;
    if (l >= L) return;
    float xv[12];
#pragma unroll
    for (int d = 0; d < 12; d++) xv[d] = xs[tid*13+d];
    for (int h = 0; h < H; h++){
        float acc = bs[h];
#pragma unroll
        for (int d = 0; d < 12; d++) acc = fmaf(xv[d], ws[h*12+d], acc);
        g_h[(b*H + h)*L + l] = acc;
    }
}

__device__ __forceinline__ void cpow79(float br, float bi, float& pr, float& pi){
    float ar = br, ai = bi;
    float xr = br, xi = bi;
#pragma unroll
    for (int s = 1; s <= 6; s++){
        float nr = xr*xr - xi*xi;
        float ni = 2.0f*xr*xi;
        xr = nr; xi = ni;
        if (s==1 || s==2 || s==3 || s==6){
            float tr = ar*xr - ai*xi;
            float ti = ar*xi + ai*xr;
            ar = tr; ai = ti;
        }
    }
    pr = ar; pi = ai;
}

// fused 3-phase chunked scan + D-skip + GELU
// cr/ci in smem (loaded per 4-step group) -> ~64 regs -> 4 CTAs/SM
__global__ __launch_bounds__(256, 4) void scan_fused_kernel(int layer, const float* __restrict__ Dp,
                                                            int do_bn){
    __shared__ float  su[L];
    __shared__ float4 sf[NC][NP+1];
    __shared__ ulonglong2 spcc[NP];      // (cr, ci) packed
    int bh  = blockIdx.x;
    int h   = bh & (H-1);
    int tid = threadIdx.x;
    int lh  = layer*H + h;
    int c = tid >> 2, q = tid & 3;

    ull rrv[4], riv[4], nriv[4];
#pragma unroll
    for (int k = 0; k < 4; k++){
        int np = q*4 + k;
        float4 p1 = g_pk1[lh*NP + np];
        float4 p2 = g_pk2[lh*NP + np];
        rrv[k]  = pk2(p1.x, p1.y);
        riv[k]  = pk2(p1.z, p1.w);
        nriv[k] = pk2(p2.x, p2.y);
    }
    if (tid < NP){
        float4 p2 = g_pk2[lh*NP + tid];
        float2 p3 = g_pk3[lh*NP + tid];
        spcc[tid] = make_ulonglong2(pk2(p2.z, p2.w), pk2(p3.x, p3.y));
    }
    float Dh  = Dp[lh];
    float bsc = do_bn ? g_bnscale[h] : 1.0f;
    float bsh = do_bn ? g_bnshift[h] : 0.0f;
    const float4* urow = (const float4*)(g_h + bh*L);
    for (int i = tid; i < L/4; i += 256){
        float4 v = urow[i];
        v.x = fmaf(v.x, bsc, bsh); v.y = fmaf(v.y, bsc, bsh);
        v.z = fmaf(v.z, bsc, bsh); v.w = fmaf(v.w, bsc, bsh);
        *(float4*)&su[i*4] = v;
    }
    __syncthreads();

    int off = c*CT;
    int Tc  = min(CT, L - off);

    ull sr[4], sti[4];
#pragma unroll
    for (int k = 0; k < 4; k++){ sr[k]=0ull; sti[k]=0ull; }

    // phase A: chunk-local final states
    if (tid < 224){
#pragma unroll 4
        for (int t = 0; t < CT; t++){
            float uv = su[off + t];
            ull uu = pk2(uv, uv);
#pragma unroll
            for (int k = 0; k < 4; k++){
                ull tmp = fma2(riv[k], sti[k], uu);
                ull m   = mul2(nriv[k], sr[k]);
                sti[k]  = fma2(rrv[k], sti[k], m);
                sr[k]   = fma2(rrv[k], sr[k], tmp);
            }
        }
    } else {
        for (int t = 0; t < Tc; t++){
            float uv = su[off + t];
            ull uu = pk2(uv, uv);
#pragma unroll
            for (int k = 0; k < 4; k++){
                ull tmp = fma2(riv[k], sti[k], uu);
                ull m   = mul2(nriv[k], sr[k]);
                sti[k]  = fma2(rrv[k], sti[k], m);
                sr[k]   = fma2(rrv[k], sr[k], tmp);
            }
        }
    }
#pragma unroll
    for (int k = 0; k < 4; k++){
        float s0,s1,ta,tb; upk2(sr[k],s0,s1); upk2(sti[k],ta,tb);
        sf[c][q*4+k] = make_float4(s0, s1, ta, tb);
    }
    __syncthreads();

    // phase B: serial boundary propagation
    if (tid < NP){
        int np = tid;
        float2 r0 = g_r[lh*N2 + np];
        float2 r1 = g_r[lh*N2 + np + 16];
        float a0r, a0i, a1r, a1i;
        cpow79(r0.x, r0.y, a0r, a0i);
        cpow79(r1.x, r1.y, a1r, a1i);
        float s0r=0.f, s0t=0.f, s1r=0.f, s1t=0.f;
        for (int c2 = 0; c2 < NC; c2++){
            float4 f = sf[c2][np];
            sf[c2][np] = make_float4(s0r, s1r, s0t, s1t);
            float n0r = a0r*s0r + a0i*s0t + f.x;
            float n0t = a0r*s0t - a0i*s0r + f.z;
            float n1r = a1r*s1r + a1i*s1t + f.y;
            float n1t = a1r*s1t - a1i*s1r + f.w;
            s0r=n0r; s0t=n0t; s1r=n1r; s1t=n1t;
        }
    }
    __syncthreads();

    // phase C: replay with output, shuffle batched x4, cc loaded per group
#pragma unroll
    for (int k = 0; k < 4; k++){
        float4 v = sf[c][q*4+k];
        sr[k]  = pk2(v.x, v.y);
        sti[k] = pk2(v.z, v.w);
    }
    if (tid < 224){
        int t = 0;
        for (int g = 0; g < 19; g++){
            ulonglong2 cc0 = spcc[q*4+0], cc1 = spcc[q*4+1];
            ulonglong2 cc2 = spcc[q*4+2], cc3 = spcc[q*4+3];
            ull crv[4] = {cc0.x, cc1.x, cc2.x, cc3.x};
            ull civ[4] = {cc0.y, cc1.y, cc2.y, cc3.y};
            float yp[4], us[4];
            us[0] = su[off+t]; us[1] = su[off+t+1]; us[2] = su[off+t+2]; us[3] = su[off+t+3];
#pragma unroll
            for (int i = 0; i < 4; i++){
                ull uu = pk2(us[i], us[i]);
                ull y2 = 0ull;
#pragma unroll
                for (int k = 0; k < 4; k++){
                    ull tmp = fma2(riv[k], sti[k], uu);
                    ull m   = mul2(nriv[k], sr[k]);
                    sti[k]  = fma2(rrv[k], sti[k], m);
                    sr[k]   = fma2(rrv[k], sr[k], tmp);
                    y2 = fma2(crv[k], sr[k], y2);
                    y2 = fma2(civ[k], sti[k], y2);
                }
                float ylo, yhi; upk2(y2, ylo, yhi);
                yp[i] = ylo + yhi;
            }
#pragma unroll
            for (int i = 0; i < 4; i++) yp[i] += __shfl_xor_sync(0xffffffffu, yp[i], 1);
#pragma unroll
            for (int i = 0; i < 4; i++) yp[i] += __shfl_xor_sync(0xffffffffu, yp[i], 2);
#pragma unroll
            for (int i = 0; i < 4; i++) su[off+t+i] = fmaf(us[i], Dh, yp[i]);
            t += 4;
        }
#pragma unroll
        for (int i = 0; i < 3; i++){
            ulonglong2 cg0 = spcc[q*4+0], cg1 = spcc[q*4+1];
            ulonglong2 cg2 = spcc[q*4+2], cg3 = spcc[q*4+3];
            ull crv[4] = {cg0.x, cg1.x, cg2.x, cg3.x};
            ull civ[4] = {cg0.y, cg1.y, cg2.y, cg3.y};
            float uv = su[off + 76 + i];
            ull uu = pk2(uv, uv);
            ull y2 = 0ull;
#pragma unroll
            for (int k = 0; k < 4; k++){
                ull tmp = fma2(riv[k], sti[k], uu);
                ull m   = mul2(nriv[k], sr[k]);
                sti[k]  = fma2(rrv[k], sti[k], m);
                sr[k]   = fma2(rrv[k], sr[k], tmp);
                y2 = fma2(crv[k], sr[k], y2);
                y2 = fma2(civ[k], sti[k], y2);
            }
            float ylo, yhi; upk2(y2, ylo, yhi);
            float y = ylo + yhi;
            y += __shfl_xor_sync(0xffffffffu, y, 1);
            y += __shfl_xor_sync(0xffffffffu, y, 2);
            su[off + 76 + i] = fmaf(uv, Dh, y);
        }
    } else {
        int t = 0;
        for (int g = 0; g < 19; g++){
            ulonglong2 cc0 = spcc[q*4+0], cc1 = spcc[q*4+1];
            ulonglong2 cc2 = spcc[q*4+2], cc3 = spcc[q*4+3];
            ull crv[4] = {cc0.x, cc1.x, cc2.x, cc3.x};
            ull civ[4] = {cc0.y, cc1.y, cc2.y, cc3.y};
            float yp[4], us[4];
#pragma unroll
            for (int i = 0; i < 4; i++){
                int idx = off + t + i;
                float uv = su[idx < L ? idx : (L-1)];
                us[i] = uv;
                ull uu = pk2(uv, uv);
                ull y2 = 0ull;
#pragma unroll
                for (int k = 0; k < 4; k++){
                    ull tmp = fma2(riv[k], sti[k], uu);
                    ull m   = mul2(nriv[k], sr[k]);
                    sti[k]  = fma2(rrv[k], sti[k], m);
                    sr[k]   = fma2(rrv[k], sr[k], tmp);
                    y2 = fma2(crv[k], sr[k], y2);
                    y2 = fma2(civ[k], sti[k], y2);
                }
                float ylo, yhi; upk2(y2, ylo, yhi);
                yp[i] = ylo + yhi;
            }
#pragma unroll
            for (int i = 0; i < 4; i++) yp[i] += __shfl_xor_sync(0xffffffffu, yp[i], 1);
#pragma unroll
            for (int i = 0; i < 4; i++) yp[i] += __shfl_xor_sync(0xffffffffu, yp[i], 2);
#pragma unroll
            for (int i = 0; i < 4; i++){
                int idx = off + t + i;
                if (idx < L) su[idx] = fmaf(us[i], Dh, yp[i]);
            }
            t += 4;
        }
#pragma unroll
        for (int i = 0; i < 3; i++){
            ulonglong2 cg0 = spcc[q*4+0], cg1 = spcc[q*4+1];
            ulonglong2 cg2 = spcc[q*4+2], cg3 = spcc[q*4+3];
            ull crv[4] = {cg0.x, cg1.x, cg2.x, cg3.x};
            ull civ[4] = {cg0.y, cg1.y, cg2.y, cg3.y};
            int idx = off + 76 + i;
            float uv = su[idx < L ? idx : (L-1)];
            ull uu = pk2(uv, uv);
            ull y2 = 0ull;
#pragma unroll
            for (int k = 0; k < 4; k++){
                ull tmp = fma2(riv[k], sti[k], uu);
                ull m   = mul2(nriv[k], sr[k]);
                sti[k]  = fma2(rrv[k], sti[k], m);
                sr[k]   = fma2(rrv[k], sr[k], tmp);
                y2 = fma2(crv[k], sr[k], y2);
                y2 = fma2(civ[k], sti[k], y2);
            }
            float ylo, yhi; upk2(y2, ylo, yhi);
            float y = ylo + yhi;
            y += __shfl_xor_sync(0xffffffffu, y, 1);
            y += __shfl_xor_sync(0xffffffffu, y, 2);
            if (idx < L) su[idx] = fmaf(uv, Dh, y);
        }
    }
    __syncthreads();

    float4* orow = (float4*)(g_yg + h*BL + (bh >> 8)*L);
    for (int i = tid; i < L/4; i += 256){
        float4 v = *(const float4*)&su[i*4];
        v.x = gelu1(v.x); v.y = gelu1(v.y); v.z = gelu1(v.z); v.w = gelu1(v.w);
        orow[i] = v;
    }
}

// 1x1 conv GEMM + GLU + BN + residual + fused BN stats (R12 geometry: 64-row tile, 2 CTAs/SM)
__global__ __launch_bounds__(256, 2) void glu_gemm_kernel(const float* __restrict__ Wg,
                                                          const float* __restrict__ bias,
                                                          int layer, int do_bn, int do_stats){
    __shared__ float Ys[2][16][128];
    __shared__ ull   Wap[2][16][66];
    __shared__ ull   Wbp[2][16][66];
    const float* Wl = Wg + layer*2*H*H;
    const float* bl = bias + layer*2*H;
    int j0 = blockIdx.x*128;
    int g0 = blockIdx.y*64;
    int tid = threadIdx.x;
    int tx = tid & 15, ty = tid >> 4;
    int wg = tid >> 2, wsub = tid & 3;
    int yr = tid >> 5, yseg = tid & 31;
    const float* ysrcA = g_yg + yr*BL + j0 + yseg*4;
    uint32_t ysA = (uint32_t)__cvta_generic_to_shared(&Ys[0][0][0]) + yr*512 + yseg*16;

    ull accA[4][4], accB[4][4];
#pragma unroll
    for (int i = 0; i < 4; i++)
#pragma unroll
        for (int cc = 0; cc < 4; cc++){ accA[i][cc]=0ull; accB[i][cc]=0ull; }

    float4 wa = *(const float4*)&Wl[(g0 + wg)*H + wsub*4];
    float4 wb = *(const float4*)&Wl[(H + g0 + wg)*H + wsub*4];
    cpa16(ysA,         ysrcA);
    cpa16(ysA + 8*512, ysrcA + 8*BL);
    cpa_commit();
    Wap[0][wsub*4+0][wg]=pk2(wa.x,wa.x); Wap[0][wsub*4+1][wg]=pk2(wa.y,wa.y);
    Wap[0][wsub*4+2][wg]=pk2(wa.z,wa.z); Wap[0][wsub*4+3][wg]=pk2(wa.w,wa.w);
    Wbp[0][wsub*4+0][wg]=pk2(wb.x,wb.x); Wbp[0][wsub*4+1][wg]=pk2(wb.y,wb.y);
    Wbp[0][wsub*4+2][wg]=pk2(wb.z,wb.z); Wbp[0][wsub*4+3][wg]=pk2(wb.w,wb.w);
    cpa_wait0();
    __syncthreads();

    for (int ko = 0; ko < H; ko += 16){
        int cur = (ko >> 4) & 1;
        bool more = (ko + 16 < H);
        if (more){
            wa = *(const float4*)&Wl[(g0 + wg)*H + (ko+16) + wsub*4];
            wb = *(const float4*)&Wl[(H + g0 + wg)*H + (ko+16) + wsub*4];
            uint32_t dst = ysA + (cur^1)*8192;
            const float* src = ysrcA + (ko+16)*BL;
            cpa16(dst,         src);
            cpa16(dst + 8*512, src + 8*BL);
            cpa_commit();
        }
        const float* Yc = &Ys[cur][0][0];
        const ull* Wac = &Wap[cur][0][0];
        const ull* Wbc = &Wbp[cur][0][0];
#pragma unroll
        for (int kk = 0; kk < 16; kk++){
            ull yv[4];
#pragma unroll
            for (int cc = 0; cc < 4; cc++) yv[cc] = *(const ull*)(Yc + kk*128 + cc*32 + tx*2);
            ulonglong2 wa01 = *(const ulonglong2*)(Wac + kk*66 + ty*4);
            ulonglong2 wa23 = *(const ulonglong2*)(Wac + kk*66 + ty*4 + 2);
            ulonglong2 wb01 = *(const ulonglong2*)(Wbc + kk*66 + ty*4);
            ulonglong2 wb23 = *(const ulonglong2*)(Wbc + kk*66 + ty*4 + 2);
            ull wa_[4] = {wa01.x, wa01.y, wa23.x, wa23.y};
            ull wb_[4] = {wb01.x, wb01.y, wb23.x, wb23.y};
#pragma unroll
            for (int i = 0; i < 4; i++)
#pragma unroll
                for (int cc = 0; cc < 4; cc++){
                    accA[i][cc] = fma2(wa_[i], yv[cc], accA[i][cc]);
                    accB[i][cc] = fma2(wb_[i], yv[cc], accB[i][cc]);
                }
        }
        if (more){
            int nxt = cur^1;
            Wap[nxt][wsub*4+0][wg]=pk2(wa.x,wa.x); Wap[nxt][wsub*4+1][wg]=pk2(wa.y,wa.y);
            Wap[nxt][wsub*4+2][wg]=pk2(wa.z,wa.z); Wap[nxt][wsub*4+3][wg]=pk2(wa.w,wa.w);
            Wbp[nxt][wsub*4+0][wg]=pk2(wb.x,wb.x); Wbp[nxt][wsub*4+1][wg]=pk2(wb.y,wb.y);
            Wbp[nxt][wsub*4+2][wg]=pk2(wb.z,wb.z); Wbp[nxt][wsub*4+3][wg]=pk2(wb.w,wb.w);
            cpa_wait0();
            __syncthreads();
        }
    }

#pragma unroll
    for (int i = 0; i < 4; i++){
        int ga = g0 + ty*4 + i;
        float ba = bl[ga], bb = bl[H + ga];
        float sc = do_bn ? g_bnscale[ga] : 1.0f;
        float sh = do_bn ? g_bnshift[ga] : 0.0f;
        double dsum = 0.0, dsq = 0.0;
#pragma unroll
        for (int cc = 0; cc < 4; cc++){
            int j = j0 + cc*32 + tx*2;
            float a0,a1,b0,b1;
            upk2(accA[i][cc], a0, a1);
            upk2(accB[i][cc], b0, b1);
            a0 += ba; a1 += ba; b0 += bb; b1 += bb;
            float gl0 = a0 * (1.0f/(1.0f+expf(-b0)));
            float gl1 = a1 * (1.0f/(1.0f+expf(-b1)));
            if (j < BL){
                int b = j / L, l = j - b*L;
                int idx = (b*H + ga)*L + l;
                float hn = fmaf(g_h[idx], sc, sh) + gl0;
                g_h[idx] = hn;
                dsum += hn; dsq += (double)hn*(double)hn;
            }
            if (j + 1 < BL){
                int b = (j+1) / L, l = (j+1) - b*L;
                int idx = (b*H + ga)*L + l;
                float hn = fmaf(g_h[idx], sc, sh) + gl1;
                g_h[idx] = hn;
                dsum += hn; dsq += (double)hn*(double)hn;
            }
        }
        if (do_stats){
#pragma unroll
            for (int o = 1; o < 16; o <<= 1){
                dsum += __shfl_xor_sync(0xffffffffu, dsum, o);
                dsq  += __shfl_xor_sync(0xffffffffu, dsq,  o);
            }
            if ((tid & 15) == 0){
                atomicAdd(&g_bnsum[ga], dsum);
                atomicAdd(&g_bnsq[ga],  dsq);
            }
        }
    }
}

__global__ void bn_finalize_kernel(const float* __restrict__ gamma, const float* __restrict__ beta,
                                   int bnidx){
    int h = threadIdx.x;
    double mean = g_bnsum[h] / (double)(NB*L);
    double var  = g_bnsq[h] / (double)(NB*L) - mean*mean;
    float scale = gamma[bnidx*H + h] * (float)(1.0 / sqrt(var + 1e-5));
    g_bnscale[h] = scale;
    g_bnshift[h] = beta[bnidx*H + h] - (float)mean * scale;
    g_bnsum[h] = 0.0;
    g_bnsq[h]  = 0.0;
}

__global__ void transpose_kernel(float* __restrict__ out){
    __shared__ float tile[32][33];
    int b = blockIdx.z;
    int l0 = blockIdx.x*32, h0 = blockIdx.y*32;
    int tx = threadIdx.x, ty = threadIdx.y;
    for (int i = ty; i < 32; i += 8){
        int l = l0 + tx;
        tile[i][tx] = (l < L) ? g_h[(b*H + h0 + i)*L + l] : 0.0f;
    }
    __syncthreads();
    for (int i = ty; i < 32; i += 8){
        int l = l0 + i;
        if (l < L) out[(b*L + l)*H + h0 + tx] = tile[tx][i];
    }
}

extern "C" void kernel_launch(void* const* d_in, const int* in_sizes, int n_in,
                              void* d_out, int out_size){
    const float* x      = (const float*)d_in[0];
    const float* pre_w  = (const float*)d_in[1];
    const float* pre_b  = (const float*)d_in[2];
    const float* log_dt = (const float*)d_in[3];
    const float* C_re   = (const float*)d_in[4];
    const float* C_im   = (const float*)d_in[5];
    const float* logA   = (const float*)d_in[6];
    const float* Aim    = (const float*)d_in[7];
    const float* Dp     = (const float*)d_in[8];
    const float* out_w  = (const float*)d_in[9];
    const float* out_b  = (const float*)d_in[10];
    const float* bn_g   = (const float*)d_in[11];
    const float* bn_b   = (const float*)d_in[12];
    float* out = (float*)d_out;

    params_kernel<<<96, 256>>>(log_dt, C_re, C_im, logA, Aim);
    preproj_kernel<<<dim3(40, 8), 128>>>(x, pre_w, pre_b);
    for (int layer = 0; layer < NL; layer++){
        int do_bn    = (layer > 0) && (((layer - 1) & 1) == 0);
        int do_stats = ((layer & 1) == 0);
        scan_fused_kernel<<<NB*H, 256>>>(layer, Dp, do_bn);
        glu_gemm_kernel<<<dim3((BL + 127)/128, 4), 256>>>(out_w, out_b, layer, do_bn, do_stats);
        if (do_stats) bn_finalize_kernel<<<1, H>>>(bn_g, bn_b, layer/2);
    }
    transpose_kernel<<<dim3((L + 31)/32, H/32, NB), dim3(32, 8)>>>(out);
}

// round 16
// speedup vs baseline: 1.0623x; 1.0623x over previous
#include <cuda_runtime.h>
#include <math.h>
#include <stdint.h>

#define NB   8
#define L    5000
#define DIN  12
#define H    256
#define N2   32
#define NL   6
#define NC   64
#define CTP  80
#define SROW 84
#define BL   (NB*L)
#define NP   16

typedef unsigned long long ull;

__device__ __forceinline__ ull fma2(ull a, ull b, ull c){ ull d; asm("fma.rn.f32x2 %0,%1,%2,%3;":"=l"(d):"l"(a),"l"(b),"l"(c)); return d; }
__device__ __forceinline__ ull mul2(ull a, ull b){ ull d; asm("mul.rn.f32x2 %0,%1,%2;":"=l"(d):"l"(a),"l"(b)); return d; }
__device__ __forceinline__ ull pk2(float lo, float hi){ ull r; asm("mov.b64 %0,{%1,%2};":"=l"(r):"f"(lo),"f"(hi)); return r; }
__device__ __forceinline__ void upk2(ull v, float& lo, float& hi){ asm("mov.b64 {%0,%1},%2;":"=f"(lo),"=f"(hi):"l"(v)); }
__device__ __forceinline__ void cpa16(uint32_t dst, const float* src){
    asm volatile("cp.async.cg.shared.global [%0], [%1], 16;"::"r"(dst),"l"(src));
}
__device__ __forceinline__ void cpa_commit(){ asm volatile("cp.async.commit_group;"); }
__device__ __forceinline__ void cpa_wait0(){ asm volatile("cp.async.wait_group 0;"); }
__device__ __forceinline__ float gelu1(float y){ return 0.5f*y*(1.0f + erff(y*0.70710678118654752f)); }

// ---- scratch ----
__device__ float  g_h[NB*H*L];
__device__ float  g_yg[H*BL + 128];
__device__ float4 g_pk1[NL*H*NP];   // rr0,rr1,ri0,ri1
__device__ float4 g_pk2[NL*H*NP];   // -ri0,-ri1,cr0,cr1
__device__ float2 g_pk3[NL*H*NP];   // ci0,ci1
__device__ float2 g_r  [NL*H*N2];
__device__ float  g_bnscale[H];
__device__ float  g_bnshift[H];
__device__ double g_bnsum[H];
__device__ double g_bnsq[H];

__global__ void params_kernel(const float* __restrict__ log_dt, const float* __restrict__ C_re,
                              const float* __restrict__ C_im, const float* __restrict__ logA,
                              const float* __restrict__ Aim){
    int idx = blockIdx.x*blockDim.x + threadIdx.x;
    if (idx >= NL*H*NP) return;
    int np = idx & (NP-1);
    int lh = idx >> 4;
    float dt = expf(log_dt[lh]);
    float rr[2], ri[2], cr[2], ci[2];
#pragma unroll
    for (int k = 0; k < 2; k++){
        int pi = lh*N2 + np + k*16;
        float Ar = -expf(logA[pi]);
        float Ai = Aim[pi];
        float er = expf(dt*Ar);
        float rre = er*cosf(dt*Ai), rim = er*sinf(dt*Ai);
        float e1r = rre - 1.0f, e1i = rim;
        float cre = C_re[pi], cim = C_im[pi];
        float tr = cre*e1r - cim*e1i;
        float ti = cre*e1i + cim*e1r;
        float inv = 1.0f/(Ar*Ar + Ai*Ai);
        float Cdr = (tr*Ar + ti*Ai)*inv;
        float Cdi = (ti*Ar - tr*Ai)*inv;
        rr[k]=rre; ri[k]=rim; cr[k]=2.0f*Cdr; ci[k]=2.0f*Cdi;
        g_r[pi] = make_float2(rre, rim);
    }
    g_pk1[idx] = make_float4(rr[0], rr[1], ri[0], ri[1]);
    g_pk2[idx] = make_float4(-ri[0], -ri[1], cr[0], cr[1]);
    g_pk3[idx] = make_float2(ci[0], ci[1]);
}

__global__ void preproj_kernel(const float* __restrict__ x, const float* __restrict__ w,
                               const float* __restrict__ bias){
    __shared__ float xs[128*13];
    __shared__ float ws[H*12];
    __shared__ float bs[H];
    int b = blockIdx.y;
    int l0 = blockIdx.x*128;
    int tid = threadIdx.x;
    for (int i = tid; i < H*12; i += 128) ws[i] = w[i];
    for (int i = tid; i < H;    i += 128) bs[i] = bias[i];
    for (int i = tid; i < 128*12; i += 128){
        int ll = i/12, d = i - ll*12;
        int l = l0 + ll;
        xs[ll*13+d] = (l < L) ? x[(b*L + l)*12 + d] : 0.0f;
    }
    __syncthreads();
    int l = l0 + tid;
    if (l >= L) return;
    float xv[12];
#pragma unroll
    for (int d = 0; d < 12; d++) xv[d] = xs[tid*13+d];
    for (int h = 0; h < H; h++){
        float acc = bs[h];
#pragma unroll
        for (int d = 0; d < 12; d++) acc = fmaf(xv[d], ws[h*12+d], acc);
        g_h[(b*H + h)*L + l] = acc;
    }
}

// r^80 = r^16 * r^64
__device__ __forceinline__ void cpow80(float br, float bi, float& pr, float& pi){
    float xr = br, xi = bi;
#pragma unroll
    for (int s = 0; s < 4; s++){          // -> r^16
        float nr = xr*xr - xi*xi;
        float ni = 2.0f*xr*xi;
        xr = nr; xi = ni;
    }
    float ar = xr, ai = xi;               // r^16
#pragma unroll
    for (int s = 0; s < 2; s++){          // -> r^64
        float nr = xr*xr - xi*xi;
        float ni = 2.0f*xr*xi;
        xr = nr; xi = ni;
    }
    pr = ar*xr - ai*xi;
    pi = ar*xi + ai*xr;
}

// fused 3-phase chunked scan (CT=80, uniform, vectorized smem) + D-skip + GELU
__global__ __launch_bounds__(256) void scan_fused_kernel(int layer, const float* __restrict__ Dp,
                                                         int do_bn){
    __shared__ float  su2[NC*SROW];      // 64 rows x 84 floats (bank-staggered)
    __shared__ float4 sf[NC][NP+1];
    int bh  = blockIdx.x;
    int h   = bh & (H-1);
    int tid = threadIdx.x;
    int lh  = layer*H + h;
    int c = tid >> 2, q = tid & 3;

    ull rrv[4], riv[4], nriv[4], crv[4], civ[4];
#pragma unroll
    for (int k = 0; k < 4; k++){
        int np = q*4 + k;
        float4 p1 = g_pk1[lh*NP + np];
        float4 p2 = g_pk2[lh*NP + np];
        float2 p3 = g_pk3[lh*NP + np];
        rrv[k]  = pk2(p1.x, p1.y);
        riv[k]  = pk2(p1.z, p1.w);
        nriv[k] = pk2(p2.x, p2.y);
        crv[k]  = pk2(p2.z, p2.w);
        civ[k]  = pk2(p3.x, p3.y);
    }
    float Dh  = Dp[lh];
    float bsc = do_bn ? g_bnscale[h] : 1.0f;
    float bsh = do_bn ? g_bnshift[h] : 0.0f;
    const float4* urow = (const float4*)(g_h + bh*L);
    // stage input into staggered 2D layout; pad tail with zeros (causal -> exact)
    for (int i = tid; i < NC*20; i += 256){
        int cc = i / 20, tg = i - cc*20;
        int l4 = cc*CTP + tg*4;
        float4 v = make_float4(0.f,0.f,0.f,0.f);
        if (l4 < L){
            v = urow[l4 >> 2];
            v.x = fmaf(v.x, bsc, bsh); v.y = fmaf(v.y, bsc, bsh);
            v.z = fmaf(v.z, bsc, bsh); v.w = fmaf(v.w, bsc, bsh);
        }
        *(float4*)&su2[cc*SROW + tg*4] = v;
    }
    __syncthreads();

    const float* myrow = su2 + c*SROW;
    ull sr[4], sti[4];
#pragma unroll
    for (int k = 0; k < 4; k++){ sr[k]=0ull; sti[k]=0ull; }

    // phase A: uniform 80 steps, 20x LDS.128
    for (int g = 0; g < 20; g++){
        float4 u4 = *(const float4*)(myrow + g*4);
        float us[4] = {u4.x, u4.y, u4.z, u4.w};
#pragma unroll
        for (int i = 0; i < 4; i++){
            ull uu = pk2(us[i], us[i]);
#pragma unroll
            for (int k = 0; k < 4; k++){
                ull tmp = fma2(riv[k], sti[k], uu);
                ull m   = mul2(nriv[k], sr[k]);
                sti[k]  = fma2(rrv[k], sti[k], m);
                sr[k]   = fma2(rrv[k], sr[k], tmp);
            }
        }
    }
#pragma unroll
    for (int k = 0; k < 4; k++){
        float s0,s1,ta,tb; upk2(sr[k],s0,s1); upk2(sti[k],ta,tb);
        sf[c][q*4+k] = make_float4(s0, s1, ta, tb);
    }
    __syncthreads();

    // phase B: serial boundary propagation with r^80
    if (tid < NP){
        int np = tid;
        float2 r0 = g_r[lh*N2 + np];
        float2 r1 = g_r[lh*N2 + np + 16];
        float a0r, a0i, a1r, a1i;
        cpow80(r0.x, r0.y, a0r, a0i);
        cpow80(r1.x, r1.y, a1r, a1i);
        float s0r=0.f, s0t=0.f, s1r=0.f, s1t=0.f;
        for (int c2 = 0; c2 < NC; c2++){
            float4 f = sf[c2][np];
            sf[c2][np] = make_float4(s0r, s1r, s0t, s1t);
            float n0r = a0r*s0r + a0i*s0t + f.x;
            float n0t = a0r*s0t - a0i*s0r + f.z;
            float n1r = a1r*s1r + a1i*s1t + f.y;
            float n1t = a1r*s1t - a1i*s1r + f.w;
            s0r=n0r; s0t=n0t; s1r=n1r; s1t=n1t;
        }
    }
    __syncthreads();

    // phase C: uniform replay, LDS.128/STS.128, shuffle batched x4
#pragma unroll
    for (int k = 0; k < 4; k++){
        float4 v = sf[c][q*4+k];
        sr[k]  = pk2(v.x, v.y);
        sti[k] = pk2(v.z, v.w);
    }
    float* myroww = su2 + c*SROW;
    for (int g = 0; g < 20; g++){
        float4 u4 = *(const float4*)(myroww + g*4);
        float us[4] = {u4.x, u4.y, u4.z, u4.w};
        float yp[4];
#pragma unroll
        for (int i = 0; i < 4; i++){
            ull uu = pk2(us[i], us[i]);
            ull y2 = 0ull;
#pragma unroll
            for (int k = 0; k < 4; k++){
                ull tmp = fma2(riv[k], sti[k], uu);
                ull m   = mul2(nriv[k], sr[k]);
                sti[k]  = fma2(rrv[k], sti[k], m);
                sr[k]   = fma2(rrv[k], sr[k], tmp);
                y2 = fma2(crv[k], sr[k], y2);
                y2 = fma2(civ[k], sti[k], y2);
            }
            float ylo, yhi; upk2(y2, ylo, yhi);
            yp[i] = ylo + yhi;
        }
#pragma unroll
        for (int i = 0; i < 4; i++) yp[i] += __shfl_xor_sync(0xffffffffu, yp[i], 1);
#pragma unroll
        for (int i = 0; i < 4; i++) yp[i] += __shfl_xor_sync(0xffffffffu, yp[i], 2);
        float4 o;
        o.x = fmaf(us[0], Dh, yp[0]); o.y = fmaf(us[1], Dh, yp[1]);
        o.z = fmaf(us[2], Dh, yp[2]); o.w = fmaf(us[3], Dh, yp[3]);
        *(float4*)(myroww + g*4) = o;
    }
    __syncthreads();

    // GELU once per element + store to GEMM layout (real L only)
    float4* orow = (float4*)(g_yg + h*BL + (bh >> 8)*L);
    for (int i = tid; i < L/4; i += 256){
        int cc = i / 20, tg = i - cc*20;
        float4 v = *(const float4*)&su2[cc*SROW + tg*4];
        v.x = gelu1(v.x); v.y = gelu1(v.y); v.z = gelu1(v.z); v.w = gelu1(v.w);
        orow[i] = v;
    }
}

// 1x1 conv GEMM + GLU + BN + residual + fused BN stats (R12 geometry)
__global__ __launch_bounds__(256, 2) void glu_gemm_kernel(const float* __restrict__ Wg,
                                                          const float* __restrict__ bias,
                                                          int layer, int do_bn, int do_stats){
    __shared__ float Ys[2][16][128];
    __shared__ ull   Wap[2][16][66];
    __shared__ ull   Wbp[2][16][66];
    const float* Wl = Wg + layer*2*H*H;
    const float* bl = bias + layer*2*H;
    int j0 = blockIdx.x*128;
    int g0 = blockIdx.y*64;
    int tid = threadIdx.x;
    int tx = tid & 15, ty = tid >> 4;
    int wg = tid >> 2, wsub = tid & 3;
    int yr = tid >> 5, yseg = tid & 31;
    const float* ysrcA = g_yg + yr*BL + j0 + yseg*4;
    uint32_t ysA = (uint32_t)__cvta_generic_to_shared(&Ys[0][0][0]) + yr*512 + yseg*16;

    ull accA[4][4], accB[4][4];
#pragma unroll
    for (int i = 0; i < 4; i++)
#pragma unroll
        for (int cc = 0; cc < 4; cc++){ accA[i][cc]=0ull; accB[i][cc]=0ull; }

    float4 wa = *(const float4*)&Wl[(g0 + wg)*H + wsub*4];
    float4 wb = *(const float4*)&Wl[(H + g0 + wg)*H + wsub*4];
    cpa16(ysA,         ysrcA);
    cpa16(ysA + 8*512, ysrcA + 8*BL);
    cpa_commit();
    Wap[0][wsub*4+0][wg]=pk2(wa.x,wa.x); Wap[0][wsub*4+1][wg]=pk2(wa.y,wa.y);
    Wap[0][wsub*4+2][wg]=pk2(wa.z,wa.z); Wap[0][wsub*4+3][wg]=pk2(wa.w,wa.w);
    Wbp[0][wsub*4+0][wg]=pk2(wb.x,wb.x); Wbp[0][wsub*4+1][wg]=pk2(wb.y,wb.y);
    Wbp[0][wsub*4+2][wg]=pk2(wb.z,wb.z); Wbp[0][wsub*4+3][wg]=pk2(wb.w,wb.w);
    cpa_wait0();
    __syncthreads();

    for (int ko = 0; ko < H; ko += 16){
        int cur = (ko >> 4) & 1;
        bool more = (ko + 16 < H);
        if (more){
            wa = *(const float4*)&Wl[(g0 + wg)*H + (ko+16) + wsub*4];
            wb = *(const float4*)&Wl[(H + g0 + wg)*H + (ko+16) + wsub*4];
            uint32_t dst = ysA + (cur^1)*8192;
            const float* src = ysrcA + (ko+16)*BL;
            cpa16(dst,         src);
            cpa16(dst + 8*512, src + 8*BL);
            cpa_commit();
        }
        const float* Yc = &Ys[cur][0][0];
        const ull* Wac = &Wap[cur][0][0];
        const ull* Wbc = &Wbp[cur][0][0];
#pragma unroll
        for (int kk = 0; kk < 16; kk++){
            ull yv[4];
#pragma unroll
            for (int cc = 0; cc < 4; cc++) yv[cc] = *(const ull*)(Yc + kk*128 + cc*32 + tx*2);
            ulonglong2 wa01 = *(const ulonglong2*)(Wac + kk*66 + ty*4);
            ulonglong2 wa23 = *(const ulonglong2*)(Wac + kk*66 + ty*4 + 2);
            ulonglong2 wb01 = *(const ulonglong2*)(Wbc + kk*66 + ty*4);
            ulonglong2 wb23 = *(const ulonglong2*)(Wbc + kk*66 + ty*4 + 2);
            ull wa_[4] = {wa01.x, wa01.y, wa23.x, wa23.y};
            ull wb_[4] = {wb01.x, wb01.y, wb23.x, wb23.y};
#pragma unroll
            for (int i = 0; i < 4; i++)
#pragma unroll
                for (int cc = 0; cc < 4; cc++){
                    accA[i][cc] = fma2(wa_[i], yv[cc], accA[i][cc]);
                    accB[i][cc] = fma2(wb_[i], yv[cc], accB[i][cc]);
                }
        }
        if (more){
            int nxt = cur^1;
            Wap[nxt][wsub*4+0][wg]=pk2(wa.x,wa.x); Wap[nxt][wsub*4+1][wg]=pk2(wa.y,wa.y);
            Wap[nxt][wsub*4+2][wg]=pk2(wa.z,wa.z); Wap[nxt][wsub*4+3][wg]=pk2(wa.w,wa.w);
            Wbp[nxt][wsub*4+0][wg]=pk2(wb.x,wb.x); Wbp[nxt][wsub*4+1][wg]=pk2(wb.y,wb.y);
            Wbp[nxt][wsub*4+2][wg]=pk2(wb.z,wb.z); Wbp[nxt][wsub*4+3][wg]=pk2(wb.w,wb.w);
            cpa_wait0();
            __syncthreads();
        }
    }

#pragma unroll
    for (int i = 0; i < 4; i++){
        int ga = g0 + ty*4 + i;
        float ba = bl[ga], bb = bl[H + ga];
        float sc = do_bn ? g_bnscale[ga] : 1.0f;
        float sh = do_bn ? g_bnshift[ga] : 0.0f;
        double dsum = 0.0, dsq = 0.0;
#pragma unroll
        for (int cc = 0; cc < 4; cc++){
            int j = j0 + cc*32 + tx*2;
            float a0,a1,b0,b1;
            upk2(accA[i][cc], a0, a1);
            upk2(accB[i][cc], b0, b1);
            a0 += ba; a1 += ba; b0 += bb; b1 += bb;
            float gl0 = a0 * (1.0f/(1.0f+expf(-b0)));
            float gl1 = a1 * (1.0f/(1.0f+expf(-b1)));
            if (j < BL){
                int b = j / L, l = j - b*L;
                int idx = (b*H + ga)*L + l;
                float hn = fmaf(g_h[idx], sc, sh) + gl0;
                g_h[idx] = hn;
                dsum += hn; dsq += (double)hn*(double)hn;
            }
            if (j + 1 < BL){
                int b = (j+1) / L, l = (j+1) - b*L;
                int idx = (b*H + ga)*L + l;
                float hn = fmaf(g_h[idx], sc, sh) + gl1;
                g_h[idx] = hn;
                dsum += hn; dsq += (double)hn*(double)hn;
            }
        }
        if (do_stats){
#pragma unroll
            for (int o = 1; o < 16; o <<= 1){
                dsum += __shfl_xor_sync(0xffffffffu, dsum, o);
                dsq  += __shfl_xor_sync(0xffffffffu, dsq,  o);
            }
            if ((tid & 15) == 0){
                atomicAdd(&g_bnsum[ga], dsum);
                atomicAdd(&g_bnsq[ga],  dsq);
            }
        }
    }
}

__global__ void bn_finalize_kernel(const float* __restrict__ gamma, const float* __restrict__ beta,
                                   int bnidx){
    int h = threadIdx.x;
    double mean = g_bnsum[h] / (double)(NB*L);
    double var  = g_bnsq[h] / (double)(NB*L) - mean*mean;
    float scale = gamma[bnidx*H + h] * (float)(1.0 / sqrt(var + 1e-5));
    g_bnscale[h] = scale;
    g_bnshift[h] = beta[bnidx*H + h] - (float)mean * scale;
    g_bnsum[h] = 0.0;
    g_bnsq[h]  = 0.0;
}

__global__ void transpose_kernel(float* __restrict__ out){
    __shared__ float tile[32][33];
    int b = blockIdx.z;
    int l0 = blockIdx.x*32, h0 = blockIdx.y*32;
    int tx = threadIdx.x, ty = threadIdx.y;
    for (int i = ty; i < 32; i += 8){
        int l = l0 + tx;
        tile[i][tx] = (l < L) ? g_h[(b*H + h0 + i)*L + l] : 0.0f;
    }
    __syncthreads();
    for (int i = ty; i < 32; i += 8){
        int l = l0 + i;
        if (l < L) out[(b*L + l)*H + h0 + tx] = tile[tx][i];
    }
}

extern "C" void kernel_launch(void* const* d_in, const int* in_sizes, int n_in,
                              void* d_out, int out_size){
    const float* x      = (const float*)d_in[0];
    const float* pre_w  = (const float*)d_in[1];
    const float* pre_b  = (const float*)d_in[2];
    const float* log_dt = (const float*)d_in[3];
    const float* C_re   = (const float*)d_in[4];
    const float* C_im   = (const float*)d_in[5];
    const float* logA   = (const float*)d_in[6];
    const float* Aim    = (const float*)d_in[7];
    const float* Dp     = (const float*)d_in[8];
    const float* out_w  = (const float*)d_in[9];
    const float* out_b  = (const float*)d_in[10];
    const float* bn_g   = (const float*)d_in[11];
    const float* bn_b   = (const float*)d_in[12];
    float* out = (float*)d_out;

    params_kernel<<<96, 256>>>(log_dt, C_re, C_im, logA, Aim);
    preproj_kernel<<<dim3(40, 8), 128>>>(x, pre_w, pre_b);
    for (int layer = 0; layer < NL; layer++){
        int do_bn    = (layer > 0) && (((layer - 1) & 1) == 0);
        int do_stats = ((layer & 1) == 0);
        scan_fused_kernel<<<NB*H, 256>>>(layer, Dp, do_bn);
        glu_gemm_kernel<<<dim3((BL + 127)/128, 4), 256>>>(out_w, out_b, layer, do_bn, do_stats);
        if (do_stats) bn_finalize_kernel<<<1, H>>>(bn_g, bn_b, layer/2);
    }
    transpose_kernel<<<dim3((L + 31)/32, H/32, NB), dim3(32, 8)>>>(out);
}